// round 12
// baseline (speedup 1.0000x reference)
#include <cuda_runtime.h>
#include <cstdint>

#define N_NODES     8192
#define N_PAIRS_MAX 1000000
#define PATH_LEN    8
#define EDGE_DIM    16
#define MAX_EDGES   100000
#define ROW_CAP     512         // Poisson mean 122/row; 512 unreachable

// Static device scratch (no allocs allowed).
__device__ float      g_T[MAX_EDGES * PATH_LEN];          // 3.2 MB (pre-scaled 1/L)
__device__ unsigned   g_cursor[N_NODES];                  // 32 KB
__device__ ulonglong2 g_rec[(size_t)N_NODES * ROW_CAP];   // 64 MB: {col, (p+1)<<32|val}

// ---------------------------------------------------------------------------
// T[e][l] = dot(edge_attr[e], edge_vector[l]) / PATH_LEN.
// Also zeroes g_cursor (folded in; saves a memset node).
// ---------------------------------------------------------------------------
__global__ void __launch_bounds__(256)
precompute_T(const float* __restrict__ edge_attr,
             const float* __restrict__ edge_vector,
             int n_edges)
{
    int e = blockIdx.x * blockDim.x + threadIdx.x;
    if (e < N_NODES) g_cursor[e] = 0u;
    if (e >= n_edges) return;

    const float4* ea = (const float4*)edge_attr + (size_t)e * 4;
    float4 a0 = __ldg(&ea[0]), a1 = __ldg(&ea[1]);
    float4 a2 = __ldg(&ea[2]), a3 = __ldg(&ea[3]);

    const float4* ev = (const float4*)edge_vector;
    float t[PATH_LEN];
#pragma unroll
    for (int l = 0; l < PATH_LEN; ++l) {
        float4 v0 = __ldg(&ev[l * 4 + 0]);
        float4 v1 = __ldg(&ev[l * 4 + 1]);
        float4 v2 = __ldg(&ev[l * 4 + 2]);
        float4 v3 = __ldg(&ev[l * 4 + 3]);
        float d = a0.x * v0.x + a0.y * v0.y + a0.z * v0.z + a0.w * v0.w
                + a1.x * v1.x + a1.y * v1.y + a1.z * v1.z + a1.w * v1.w
                + a2.x * v2.x + a2.y * v2.y + a2.z * v2.z + a2.w * v2.w
                + a3.x * v3.x + a3.y * v3.y + a3.z * v3.z + a3.w * v3.w;
        t[l] = d * (1.0f / PATH_LEN);
    }
    float4* tt = (float4*)(g_T + (size_t)e * PATH_LEN);
    tt[0] = make_float4(t[0], t[1], t[2], t[3]);
    tt[1] = make_float4(t[4], t[5], t[6], t[7]);
}

// ---------------------------------------------------------------------------
// 4 pairs per thread. Record carries the value: {col, (p+1)<<32 | val_bits}.
// (Gather phase is L2-BW bound; structure at its floor.)
// ---------------------------------------------------------------------------
__global__ void __launch_bounds__(256)
scatter_dots4(const int* __restrict__ paths,
              const int* __restrict__ src,
              const int* __restrict__ dst,
              int n_pairs)
{
    int t  = blockIdx.x * blockDim.x + threadIdx.x;
    int p0 = t * 4;
    if (p0 >= n_pairs) return;
    int nrem = n_pairs - p0;                 // >= 1

    const int4* pp = (const int4*)paths + (size_t)p0 * 2;
    int4 pr[8];
#pragma unroll
    for (int k = 0; k < 4; ++k) {
        if (k < nrem) {
            pr[2 * k + 0] = __ldg(&pp[2 * k + 0]);
            pr[2 * k + 1] = __ldg(&pp[2 * k + 1]);
        } else {
            pr[2 * k + 0] = make_int4(-1, -1, -1, -1);
            pr[2 * k + 1] = make_int4(-1, -1, -1, -1);
        }
    }

    int s[4], d[4];
    if (nrem >= 4) {
        int4 s4 = __ldg((const int4*)(src + p0));
        int4 d4 = __ldg((const int4*)(dst + p0));
        s[0] = s4.x; s[1] = s4.y; s[2] = s4.z; s[3] = s4.w;
        d[0] = d4.x; d[1] = d4.y; d[2] = d4.z; d[3] = d4.w;
    } else {
#pragma unroll
        for (int k = 0; k < 4; ++k) {
            s[k] = (k < nrem) ? src[p0 + k] : 0;
            d[k] = (k < nrem) ? dst[p0 + k] : 0;
        }
    }

    float sum[4] = {0.f, 0.f, 0.f, 0.f};
#pragma unroll
    for (int l = 0; l < PATH_LEN; ++l) {
#pragma unroll
        for (int k = 0; k < 4; ++k) {
            const int* ik = (const int*)&pr[2 * k];
            int e = ik[l];
            if (e >= 0) sum[k] += __ldg(&g_T[(size_t)e * PATH_LEN + l]);
        }
    }

#pragma unroll
    for (int k = 0; k < 4; ++k) {
        if (k < nrem) {
            unsigned row = (unsigned)s[k];
            unsigned pos = atomicAdd(&g_cursor[row], 1u);
            if (pos < ROW_CAP) {
                unsigned long long key =
                    ((unsigned long long)(unsigned)(p0 + k + 1) << 32) |
                    (unsigned long long)__float_as_uint(sum[k]);
                g_rec[(size_t)row * ROW_CAP + pos] =
                    make_ulonglong2((unsigned long long)(unsigned)d[k], key);
            }
        }
    }
}

// ---------------------------------------------------------------------------
// One block (256 thr, 32KB smem) per row.
//   Pass A: atomicMax(tag[col], p+1)   (winner = max pair idx == JAX order)
//   Pass B: unique winner overwrites tag[col] with val_bits.
//           Safe: val_bits in [1,1e6] would mean |val| < 1.4e-39 (subnormal,
//           unreachable); exact 0.0 -> bits 0 != any p+1.
//   Pass C: ONE TMA bulk store (32KB smem -> gmem) — no per-thread stores.
// ---------------------------------------------------------------------------
__global__ void __launch_bounds__(256)
write_rows(float* __restrict__ out)
{
    __shared__ __align__(128) unsigned tag[N_NODES];   // 32 KB

    const unsigned row = blockIdx.x;
    const unsigned tid = threadIdx.x;

    // issue cursor read first; latency hides under the smem zeroing
    unsigned cnt = g_cursor[row];

    uint4* tag4 = (uint4*)tag;
#pragma unroll
    for (int j = 0; j < (N_NODES / 4) / 256; ++j)       // 8 uint4 per thread
        tag4[tid + j * 256] = make_uint4(0u, 0u, 0u, 0u);
    __syncthreads();

    if (cnt > ROW_CAP) cnt = ROW_CAP;

    unsigned col[2], pw[2], vb[2];
    bool have[2];
    const ulonglong2* rec = g_rec + (size_t)row * ROW_CAP;
#pragma unroll
    for (int q = 0; q < 2; ++q) {
        unsigned r = tid + q * 256;
        have[q] = (r < cnt);
        if (have[q]) {
            ulonglong2 e = __ldg(&rec[r]);
            col[q] = (unsigned)e.x;
            pw[q]  = (unsigned)(e.y >> 32);
            vb[q]  = (unsigned)e.y;
            atomicMax(&tag[col[q]], pw[q]);
        }
    }
    __syncthreads();

#pragma unroll
    for (int q = 0; q < 2; ++q)
        if (have[q] && tag[col[q]] == pw[q]) tag[col[q]] = vb[q];
    __syncthreads();

    // Pass C: single bulk async store of the whole row.
    if (tid == 0) {
        // order generic-proxy smem writes (visible after syncthreads) before
        // the async-proxy read
        asm volatile("fence.proxy.async.shared::cta;" ::: "memory");
        uint32_t saddr;
        asm("{ .reg .u64 t; cvta.to.shared.u64 t, %1; cvt.u32.u64 %0, t; }"
            : "=r"(saddr) : "l"((const void*)tag));
        float* dstp = out + (size_t)row * N_NODES;
        asm volatile(
            "cp.async.bulk.global.shared::cta.bulk_group [%0], [%1], %2;"
            :: "l"(dstp), "r"(saddr), "n"(N_NODES * 4) : "memory");
        asm volatile("cp.async.bulk.commit_group;" ::: "memory");
        // wait for smem reads to complete before the block (and its smem) retires
        asm volatile("cp.async.bulk.wait_group.read 0;" ::: "memory");
    }
}

// ---------------------------------------------------------------------------
extern "C" void kernel_launch(void* const* d_in, const int* in_sizes, int n_in,
                              void* d_out, int out_size)
{
    int off = (in_sizes[0] == 1) ? 1 : 0;

    const float* edge_attr   = (const float*)d_in[off + 0];
    const int*   src         = (const int*)  d_in[off + 1];
    const int*   dst         = (const int*)  d_in[off + 2];
    const int*   paths       = (const int*)  d_in[off + 3];
    const float* edge_vector = (const float*)d_in[off + 4];
    float* out = (float*)d_out;

    const int n_edges = in_sizes[off + 0] / EDGE_DIM;
    const int n_pairs = in_sizes[off + 1];

    precompute_T<<<(n_edges + 255) / 256, 256>>>(edge_attr, edge_vector, n_edges);

    const int n_thr = (n_pairs + 3) / 4;
    scatter_dots4<<<(n_thr + 255) / 256, 256>>>(paths, src, dst, n_pairs);

    write_rows<<<N_NODES, 256>>>(out);
}

// round 13
// speedup vs baseline: 1.0289x; 1.0289x over previous
#include <cuda_runtime.h>
#include <cstdint>

#define N_NODES     8192
#define N_PAIRS_MAX 1000000
#define PATH_LEN    8
#define EDGE_DIM    16
#define MAX_EDGES   100000
#define ROW_CAP     512         // Poisson mean 122/row; 512 unreachable

// Record packing: [p+1 : 20 bits][col : 13 bits][val>>1 : 31 bits]
//  - max over same-cell records == max over p+1 (top bits)  [col equal]
//  - val reconstructed as (low31 << 1): drops fp32 mantissa LSB (<=1 ulp)
// Static device scratch (no allocs allowed).
__device__ float              g_T[MAX_EDGES * PATH_LEN];        // 3.2 MB (pre-scaled 1/L)
__device__ unsigned           g_cursor[N_NODES];                // 32 KB
__device__ unsigned long long g_rec[(size_t)N_NODES * ROW_CAP]; // 32 MB

// ---------------------------------------------------------------------------
// T[e][l] = dot(edge_attr[e], edge_vector[l]) / PATH_LEN. Also zeroes cursor.
// ---------------------------------------------------------------------------
__global__ void __launch_bounds__(256)
precompute_T(const float* __restrict__ edge_attr,
             const float* __restrict__ edge_vector,
             int n_edges)
{
    int e = blockIdx.x * blockDim.x + threadIdx.x;
    if (e < N_NODES) g_cursor[e] = 0u;
    if (e >= n_edges) return;

    const float4* ea = (const float4*)edge_attr + (size_t)e * 4;
    float4 a0 = __ldg(&ea[0]), a1 = __ldg(&ea[1]);
    float4 a2 = __ldg(&ea[2]), a3 = __ldg(&ea[3]);

    const float4* ev = (const float4*)edge_vector;
    float t[PATH_LEN];
#pragma unroll
    for (int l = 0; l < PATH_LEN; ++l) {
        float4 v0 = __ldg(&ev[l * 4 + 0]);
        float4 v1 = __ldg(&ev[l * 4 + 1]);
        float4 v2 = __ldg(&ev[l * 4 + 2]);
        float4 v3 = __ldg(&ev[l * 4 + 3]);
        float d = a0.x * v0.x + a0.y * v0.y + a0.z * v0.z + a0.w * v0.w
                + a1.x * v1.x + a1.y * v1.y + a1.z * v1.z + a1.w * v1.w
                + a2.x * v2.x + a2.y * v2.y + a2.z * v2.z + a2.w * v2.w
                + a3.x * v3.x + a3.y * v3.y + a3.z * v3.z + a3.w * v3.w;
        t[l] = d * (1.0f / PATH_LEN);
    }
    float4* tt = (float4*)(g_T + (size_t)e * PATH_LEN);
    tt[0] = make_float4(t[0], t[1], t[2], t[3]);
    tt[1] = make_float4(t[4], t[5], t[6], t[7]);
}

// ---------------------------------------------------------------------------
// 4 pairs per thread. 8-byte packed record per pair.
// ---------------------------------------------------------------------------
__global__ void __launch_bounds__(256)
scatter_dots4(const int* __restrict__ paths,
              const int* __restrict__ src,
              const int* __restrict__ dst,
              int n_pairs)
{
    int t  = blockIdx.x * blockDim.x + threadIdx.x;
    int p0 = t * 4;
    if (p0 >= n_pairs) return;
    int nrem = n_pairs - p0;                 // >= 1

    const int4* pp = (const int4*)paths + (size_t)p0 * 2;
    int4 pr[8];
#pragma unroll
    for (int k = 0; k < 4; ++k) {
        if (k < nrem) {
            pr[2 * k + 0] = __ldg(&pp[2 * k + 0]);
            pr[2 * k + 1] = __ldg(&pp[2 * k + 1]);
        } else {
            pr[2 * k + 0] = make_int4(-1, -1, -1, -1);
            pr[2 * k + 1] = make_int4(-1, -1, -1, -1);
        }
    }

    int s[4], d[4];
    if (nrem >= 4) {
        int4 s4 = __ldg((const int4*)(src + p0));
        int4 d4 = __ldg((const int4*)(dst + p0));
        s[0] = s4.x; s[1] = s4.y; s[2] = s4.z; s[3] = s4.w;
        d[0] = d4.x; d[1] = d4.y; d[2] = d4.z; d[3] = d4.w;
    } else {
#pragma unroll
        for (int k = 0; k < 4; ++k) {
            s[k] = (k < nrem) ? src[p0 + k] : 0;
            d[k] = (k < nrem) ? dst[p0 + k] : 0;
        }
    }

    float sum[4] = {0.f, 0.f, 0.f, 0.f};
#pragma unroll
    for (int l = 0; l < PATH_LEN; ++l) {
#pragma unroll
        for (int k = 0; k < 4; ++k) {
            const int* ik = (const int*)&pr[2 * k];
            int e = ik[l];
            if (e >= 0) sum[k] += __ldg(&g_T[(size_t)e * PATH_LEN + l]);
        }
    }

#pragma unroll
    for (int k = 0; k < 4; ++k) {
        if (k < nrem) {
            unsigned row = (unsigned)s[k];
            unsigned pos = atomicAdd(&g_cursor[row], 1u);
            if (pos < ROW_CAP) {
                unsigned long long rec =
                    ((unsigned long long)(unsigned)(p0 + k + 1) << 44) |
                    ((unsigned long long)(unsigned)d[k] << 31) |
                    (unsigned long long)(__float_as_uint(sum[k]) >> 1);
                g_rec[(size_t)row * ROW_CAP + pos] = rec;
            }
        }
    }
}

// ---------------------------------------------------------------------------
// One block (256 thr, 32KB smem) per row (proven R11 form).
//   Pass A: atomicMax(tag[col], p+1)
//   Pass B: unique winner overwrites tag[col] with val_bits (reconstructed).
//           Safe: val_bits in [1,1e6] would mean |val| < 1.4e-39 (subnormal,
//           unreachable); exact 0.0 -> bits 0 != any p+1.
//   Pass C: per-thread streaming STG.128 (TMA flush was slower: R12).
// ---------------------------------------------------------------------------
__global__ void __launch_bounds__(256)
write_rows(float* __restrict__ out)
{
    __shared__ unsigned tag[N_NODES];   // 32 KB

    const unsigned row = blockIdx.x;
    const unsigned tid = threadIdx.x;

    unsigned cnt = g_cursor[row];       // latency hides under smem zeroing

    uint4* tag4 = (uint4*)tag;
#pragma unroll
    for (int j = 0; j < (N_NODES / 4) / 256; ++j)
        tag4[tid + j * 256] = make_uint4(0u, 0u, 0u, 0u);
    __syncthreads();

    if (cnt > ROW_CAP) cnt = ROW_CAP;

    unsigned col[2], pw[2], vb[2];
    bool have[2];
    const unsigned long long* rec = g_rec + (size_t)row * ROW_CAP;
#pragma unroll
    for (int q = 0; q < 2; ++q) {
        unsigned r = tid + q * 256;
        have[q] = (r < cnt);
        if (have[q]) {
            unsigned long long e = __ldg(&rec[r]);
            pw[q]  = (unsigned)(e >> 44);                    // p+1 (20 bits)
            col[q] = (unsigned)(e >> 31) & 0x1FFFu;          // col (13 bits)
            vb[q]  = ((unsigned)e & 0x7FFFFFFFu) << 1;       // val bits
            atomicMax(&tag[col[q]], pw[q]);
        }
    }
    __syncthreads();

#pragma unroll
    for (int q = 0; q < 2; ++q)
        if (have[q] && tag[col[q]] == pw[q]) tag[col[q]] = vb[q];
    __syncthreads();

    float4* orow = (float4*)(out + (size_t)row * N_NODES);
#pragma unroll
    for (int j = 0; j < (N_NODES / 4) / 256; ++j) {
        unsigned i = tid + j * 256;
        uint4 tv = tag4[i];
        float4 v;
        v.x = __uint_as_float(tv.x);
        v.y = __uint_as_float(tv.y);
        v.z = __uint_as_float(tv.z);
        v.w = __uint_as_float(tv.w);
        __stcs(&orow[i], v);
    }
}

// ---------------------------------------------------------------------------
extern "C" void kernel_launch(void* const* d_in, const int* in_sizes, int n_in,
                              void* d_out, int out_size)
{
    int off = (in_sizes[0] == 1) ? 1 : 0;

    const float* edge_attr   = (const float*)d_in[off + 0];
    const int*   src         = (const int*)  d_in[off + 1];
    const int*   dst         = (const int*)  d_in[off + 2];
    const int*   paths       = (const int*)  d_in[off + 3];
    const float* edge_vector = (const float*)d_in[off + 4];
    float* out = (float*)d_out;

    const int n_edges = in_sizes[off + 0] / EDGE_DIM;
    const int n_pairs = in_sizes[off + 1];

    precompute_T<<<(n_edges + 255) / 256, 256>>>(edge_attr, edge_vector, n_edges);

    const int n_thr = (n_pairs + 3) / 4;
    scatter_dots4<<<(n_thr + 255) / 256, 256>>>(paths, src, dst, n_pairs);

    write_rows<<<N_NODES, 256>>>(out);
}

// round 14
// speedup vs baseline: 1.0782x; 1.0479x over previous
#include <cuda_runtime.h>
#include <cstdint>

#define N_NODES     8192
#define N_PAIRS_MAX 1000000
#define PATH_LEN    8
#define EDGE_DIM    16
#define MAX_EDGES   100000
#define ROW_CAP     512         // Poisson mean 122/row; 512 unreachable

// Record packing: [p+1 : 20][col : 13][val>>1 : 31]
//  - max over same-cell records == max over p+1 (top bits; col equal)
//  - val reconstructed as (low31 << 1): drops fp32 mantissa LSB (<=1 ulp)
__device__ float              g_T[MAX_EDGES * PATH_LEN];        // 3.2 MB (pre-scaled 1/L)
__device__ unsigned           g_cursor[N_NODES];                // 32 KB
__device__ unsigned long long g_rec[(size_t)N_NODES * ROW_CAP]; // 32 MB

__device__ __forceinline__ void gdc_wait() {
    asm volatile("griddepcontrol.wait;" ::: "memory");
}
__device__ __forceinline__ void gdc_launch_dependents() {
    asm volatile("griddepcontrol.launch_dependents;" ::: "memory");
}

// ---------------------------------------------------------------------------
// T[e][l] = dot(edge_attr[e], edge_vector[l]) / PATH_LEN. Also zeroes cursor.
// Fires launch_dependents early: scatter's input loads overlap this kernel.
// ---------------------------------------------------------------------------
__global__ void __launch_bounds__(256)
precompute_T(const float* __restrict__ edge_attr,
             const float* __restrict__ edge_vector,
             int n_edges)
{
    gdc_launch_dependents();

    int e = blockIdx.x * blockDim.x + threadIdx.x;
    if (e < N_NODES) g_cursor[e] = 0u;
    if (e >= n_edges) return;

    const float4* ea = (const float4*)edge_attr + (size_t)e * 4;
    float4 a0 = __ldg(&ea[0]), a1 = __ldg(&ea[1]);
    float4 a2 = __ldg(&ea[2]), a3 = __ldg(&ea[3]);

    const float4* ev = (const float4*)edge_vector;
    float t[PATH_LEN];
#pragma unroll
    for (int l = 0; l < PATH_LEN; ++l) {
        float4 v0 = __ldg(&ev[l * 4 + 0]);
        float4 v1 = __ldg(&ev[l * 4 + 1]);
        float4 v2 = __ldg(&ev[l * 4 + 2]);
        float4 v3 = __ldg(&ev[l * 4 + 3]);
        float d = a0.x * v0.x + a0.y * v0.y + a0.z * v0.z + a0.w * v0.w
                + a1.x * v1.x + a1.y * v1.y + a1.z * v1.z + a1.w * v1.w
                + a2.x * v2.x + a2.y * v2.y + a2.z * v2.z + a2.w * v2.w
                + a3.x * v3.x + a3.y * v3.y + a3.z * v3.z + a3.w * v3.w;
        t[l] = d * (1.0f / PATH_LEN);
    }
    float4* tt = (float4*)(g_T + (size_t)e * PATH_LEN);
    tt[0] = make_float4(t[0], t[1], t[2], t[3]);
    tt[1] = make_float4(t[4], t[5], t[6], t[7]);
}

// ---------------------------------------------------------------------------
// 4 pairs per thread. PDL: all input loads (paths/src/dst — 40 MB) are issued
// BEFORE griddepcontrol.wait, overlapping precompute_T. T-dependent work
// (gathers, cursor atomics, records) happens after the wait.
// ---------------------------------------------------------------------------
__global__ void __launch_bounds__(256)
scatter_dots4(const int* __restrict__ paths,
              const int* __restrict__ src,
              const int* __restrict__ dst,
              int n_pairs)
{
    int t  = blockIdx.x * blockDim.x + threadIdx.x;
    int p0 = t * 4;
    int nrem = n_pairs - p0;                 // may be <= 0

    // ---- pre-dependency phase: load everything that doesn't need T ----
    int4 pr[8];
    int s[4], d[4];
    if (nrem > 0) {
        const int4* pp = (const int4*)paths + (size_t)p0 * 2;
#pragma unroll
        for (int k = 0; k < 4; ++k) {
            if (k < nrem) {
                pr[2 * k + 0] = __ldg(&pp[2 * k + 0]);
                pr[2 * k + 1] = __ldg(&pp[2 * k + 1]);
            } else {
                pr[2 * k + 0] = make_int4(-1, -1, -1, -1);
                pr[2 * k + 1] = make_int4(-1, -1, -1, -1);
            }
        }
        if (nrem >= 4) {
            int4 s4 = __ldg((const int4*)(src + p0));
            int4 d4 = __ldg((const int4*)(dst + p0));
            s[0] = s4.x; s[1] = s4.y; s[2] = s4.z; s[3] = s4.w;
            d[0] = d4.x; d[1] = d4.y; d[2] = d4.z; d[3] = d4.w;
        } else {
#pragma unroll
            for (int k = 0; k < 4; ++k) {
                s[k] = (k < nrem) ? src[p0 + k] : 0;
                d[k] = (k < nrem) ? dst[p0 + k] : 0;
            }
        }
    }

    // ---- wait for precompute_T grid (g_T + zeroed g_cursor visible) ----
    gdc_wait();

    if (nrem <= 0) { gdc_launch_dependents(); return; }

    float sum[4] = {0.f, 0.f, 0.f, 0.f};
#pragma unroll
    for (int l = 0; l < PATH_LEN; ++l) {
#pragma unroll
        for (int k = 0; k < 4; ++k) {
            const int* ik = (const int*)&pr[2 * k];
            int e = ik[l];
            if (e >= 0) sum[k] += __ldg(&g_T[(size_t)e * PATH_LEN + l]);
        }
    }

    // allow write_rows blocks to launch & zero their smem during record phase
    gdc_launch_dependents();

#pragma unroll
    for (int k = 0; k < 4; ++k) {
        if (k < nrem) {
            unsigned row = (unsigned)s[k];
            unsigned pos = atomicAdd(&g_cursor[row], 1u);
            if (pos < ROW_CAP) {
                unsigned long long rec =
                    ((unsigned long long)(unsigned)(p0 + k + 1) << 44) |
                    ((unsigned long long)(unsigned)d[k] << 31) |
                    (unsigned long long)(__float_as_uint(sum[k]) >> 1);
                g_rec[(size_t)row * ROW_CAP + pos] = rec;
            }
        }
    }
}

// ---------------------------------------------------------------------------
// One block (256 thr, 32KB smem) per row. PDL: smem zeroing happens BEFORE
// the wait (overlaps scatter tail); cursor/record reads after.
//   Pass A: atomicMax(tag[col], p+1)   Pass B: winner installs val bits.
//   Safe: val_bits in [1,1e6] would mean |val| < 1.4e-39 (unreachable);
//   exact 0.0 -> bits 0 != any p+1.
//   Pass C: per-thread streaming STG.128.
// ---------------------------------------------------------------------------
__global__ void __launch_bounds__(256)
write_rows(float* __restrict__ out)
{
    __shared__ unsigned tag[N_NODES];   // 32 KB

    const unsigned row = blockIdx.x;
    const unsigned tid = threadIdx.x;

    // pre-dependency: zero tags
    uint4* tag4 = (uint4*)tag;
#pragma unroll
    for (int j = 0; j < (N_NODES / 4) / 256; ++j)
        tag4[tid + j * 256] = make_uint4(0u, 0u, 0u, 0u);

    gdc_wait();          // scatter grid complete: cursor/records visible
    __syncthreads();

    unsigned cnt = g_cursor[row];
    if (cnt > ROW_CAP) cnt = ROW_CAP;

    unsigned col[2], pw[2], vb[2];
    bool have[2];
    const unsigned long long* rec = g_rec + (size_t)row * ROW_CAP;
#pragma unroll
    for (int q = 0; q < 2; ++q) {
        unsigned r = tid + q * 256;
        have[q] = (r < cnt);
        if (have[q]) {
            unsigned long long e = __ldg(&rec[r]);
            pw[q]  = (unsigned)(e >> 44);
            col[q] = (unsigned)(e >> 31) & 0x1FFFu;
            vb[q]  = ((unsigned)e & 0x7FFFFFFFu) << 1;
            atomicMax(&tag[col[q]], pw[q]);
        }
    }
    __syncthreads();

#pragma unroll
    for (int q = 0; q < 2; ++q)
        if (have[q] && tag[col[q]] == pw[q]) tag[col[q]] = vb[q];
    __syncthreads();

    float4* orow = (float4*)(out + (size_t)row * N_NODES);
#pragma unroll
    for (int j = 0; j < (N_NODES / 4) / 256; ++j) {
        unsigned i = tid + j * 256;
        uint4 tv = tag4[i];
        float4 v;
        v.x = __uint_as_float(tv.x);
        v.y = __uint_as_float(tv.y);
        v.z = __uint_as_float(tv.z);
        v.w = __uint_as_float(tv.w);
        __stcs(&orow[i], v);
    }
}

// ---------------------------------------------------------------------------
extern "C" void kernel_launch(void* const* d_in, const int* in_sizes, int n_in,
                              void* d_out, int out_size)
{
    int off = (in_sizes[0] == 1) ? 1 : 0;

    const float* edge_attr   = (const float*)d_in[off + 0];
    const int*   src         = (const int*)  d_in[off + 1];
    const int*   dst         = (const int*)  d_in[off + 2];
    const int*   paths       = (const int*)  d_in[off + 3];
    const float* edge_vector = (const float*)d_in[off + 4];
    float* out = (float*)d_out;

    const int n_edges = in_sizes[off + 0] / EDGE_DIM;
    const int n_pairs = in_sizes[off + 1];

    // Kernel 1: plain launch.
    precompute_T<<<(n_edges + 255) / 256, 256>>>(edge_attr, edge_vector, n_edges);

    // PDL attribute for the two dependent launches.
    cudaLaunchAttribute attrs[1];
    attrs[0].id = cudaLaunchAttributeProgrammaticStreamSerialization;
    attrs[0].val.programmaticStreamSerializationAllowed = 1;

    {   // Kernel 2: scatter (dependent on T)
        const int n_thr = (n_pairs + 3) / 4;
        cudaLaunchConfig_t cfg = {};
        cfg.gridDim  = dim3((n_thr + 255) / 256, 1, 1);
        cfg.blockDim = dim3(256, 1, 1);
        cfg.stream   = 0;
        cfg.attrs    = attrs;
        cfg.numAttrs = 1;
        cudaLaunchKernelEx(&cfg, scatter_dots4, paths, src, dst, n_pairs);
    }

    {   // Kernel 3: write_rows (dependent on scatter)
        cudaLaunchConfig_t cfg = {};
        cfg.gridDim  = dim3(N_NODES, 1, 1);
        cfg.blockDim = dim3(256, 1, 1);
        cfg.stream   = 0;
        cfg.attrs    = attrs;
        cfg.numAttrs = 1;
        cudaLaunchKernelEx(&cfg, write_rows, out);
    }
}